// round 1
// baseline (speedup 1.0000x reference)
#include <cuda_runtime.h>
#include <math.h>

// Problem constants
#define NB       128
#define TLEN     160000
#define NFFT     400
#define HOP      160
#define NFRAMES  1001          // 1 + TLEN/HOP
#define NFREQ    201           // NFFT/2 + 1
#define NMELS    80
#define FPB      16            // frames per block
#define NTILES   ((NFRAMES + FPB - 1) / FPB)   // 63
#define NH       199           // symmetric half: n = 1..199
#define NTHREADS 224
#define SPAN     (HOP * (FPB - 1) + NFFT)      // 2800 samples per block

// (cos, sin) twiddles, window NOT folded (folded into e/o instead).
// One extra zero row so the software-pipelined prefetch can read row NH safely.
__device__ float2 g_cs[(NH + 1) * NFREQ];
// Nonzero [start, end) freq range per mel filter (triangles are sparse).
__device__ int2 g_mrange[NMELS];

__global__ void setup_cs_kernel() {
    int idx = blockIdx.x * blockDim.x + threadIdx.x;
    if (idx >= NH * NFREQ) return;
    int n = idx / NFREQ + 1;            // 1..199
    int k = idx - (n - 1) * NFREQ;      // 0..200
    int r = (n * k) % NFFT;             // exact integer phase reduction
    double a = (double)r * (6.283185307179586476925286766559 / (double)NFFT);
    g_cs[idx] = make_float2((float)cos(a), (float)sin(a));
}

__global__ void setup_mrange_kernel(const float* __restrict__ fb) {
    int m = threadIdx.x;
    if (m >= NMELS) return;
    int ks = NFREQ, ke = 0;
    for (int k = 0; k < NFREQ; k++) {
        if (fb[m * NFREQ + k] != 0.0f) { if (k < ks) ks = k; ke = k + 1; }
    }
    if (ke < ks) { ks = 0; ke = 0; }
    g_mrange[m] = make_int2(ks, ke);
}

__global__ __launch_bounds__(NTHREADS)
void melspec_kernel(const float* __restrict__ audio,
                    const float* __restrict__ window,
                    const float* __restrict__ fb,
                    float* __restrict__ out) {
    // s_u is a union: phase 1 holds raw samples (2800 f32),
    // phase 3 holds the power spectrum (16*201 = 3216 f32).
    __shared__ float  s_u[FPB * NFREQ];
    __shared__ float2 s_eo[NH * FPB];   // (e, o) per (n, frame): 25.4 KB
    __shared__ float  s_x0[FPB];
    __shared__ float  s_x200[FPB];

    const int tid    = threadIdx.x;
    const int b      = blockIdx.y;
    const int tile   = blockIdx.x;
    const int frame0 = tile * FPB;
    const float* x   = audio + (size_t)b * TLEN;
    const int base   = frame0 * HOP - (NFFT / 2);

    // ---- Phase 1: load raw samples with reflect padding ----
    for (int i = tid; i < SPAN; i += NTHREADS) {
        int j = base + i;
        if (j < 0) j = -j;
        else if (j >= TLEN) j = 2 * TLEN - 2 - j;
        s_u[i] = x[j];
    }
    __syncthreads();

    // ---- Phase 2: even/odd windowed combinations ----
    if (tid < FPB) {
        s_x0[tid]   = window[0]        * s_u[tid * HOP];
        s_x200[tid] = window[NFFT / 2] * s_u[tid * HOP + NFFT / 2];
    }
    for (int idx = tid; idx < NH * FPB; idx += NTHREADS) {
        int n = (idx >> 4) + 1;          // FPB == 16
        int f = idx & (FPB - 1);
        float w = window[n];
        float a = s_u[f * HOP + n];
        float c = s_u[f * HOP + NFFT - n];
        s_eo[idx] = make_float2(w * (a + c), w * (a - c));
    }
    __syncthreads();

    // ---- Phase 3: half-length real DFT, 16 frames per thread ----
    float re[FPB], im[FPB];
    const int k = tid;
    if (k < NFREQ) {
        float sgn = (k & 1) ? -1.0f : 1.0f;
        #pragma unroll
        for (int f = 0; f < FPB; f++) {
            re[f] = s_x0[f] + sgn * s_x200[f];
            im[f] = 0.0f;
        }
        const float2* csp = g_cs + k;
        float2 cs = csp[0];
        for (int n = 0; n < NH; n++) {
            float2 csn = csp[(n + 1) * NFREQ];    // prefetch (row NH is zeros)
            const float4* eo4 = (const float4*)(s_eo + n * FPB);
            #pragma unroll
            for (int h = 0; h < FPB / 2; h++) {
                float4 v = eo4[h];                 // {e0,o0,e1,o1}, smem broadcast
                re[2*h]   = fmaf(cs.x, v.x, re[2*h]);
                im[2*h]   = fmaf(cs.y, v.y, im[2*h]);
                re[2*h+1] = fmaf(cs.x, v.z, re[2*h+1]);
                im[2*h+1] = fmaf(cs.y, v.w, im[2*h+1]);
            }
            cs = csn;
        }
    }
    __syncthreads();      // s_u (raw samples) is dead; reuse for power
    if (k < NFREQ) {
        #pragma unroll
        for (int f = 0; f < FPB; f++)
            s_u[f * NFREQ + k] = re[f] * re[f] + im[f] * im[f];
    }
    __syncthreads();

    // ---- Phase 4: sparse mel projection + log ----
    const int f  = tid & (FPB - 1);
    const int mb = tid >> 4;                         // 0..13
    int nvalid = NFRAMES - frame0;
    if (nvalid > FPB) nvalid = FPB;
    for (int m = mb; m < NMELS; m += NTHREADS / FPB) {
        int2 r = g_mrange[m];
        float acc = 0.0f;
        const float* fbr = fb  + m * NFREQ;
        const float* pr  = s_u + f * NFREQ;
        for (int kk = r.x; kk < r.y; kk++)
            acc = fmaf(fbr[kk], pr[kk], acc);
        if (f < nvalid)
            out[((size_t)b * NMELS + m) * NFRAMES + frame0 + f] =
                logf(acc + 1.1920929e-07f);
    }
}

extern "C" void kernel_launch(void* const* d_in, const int* in_sizes, int n_in,
                              void* d_out, int out_size) {
    const float* audio  = (const float*)d_in[0];
    const float* window = (const float*)d_in[1];
    const float* fb     = (const float*)d_in[2];
    float* out          = (float*)d_out;

    setup_cs_kernel<<<(NH * NFREQ + 255) / 256, 256>>>();
    setup_mrange_kernel<<<1, NMELS>>>(fb);

    dim3 grid(NTILES, NB);
    melspec_kernel<<<grid, NTHREADS>>>(audio, window, fb, out);
}

// round 2
// speedup vs baseline: 1.2109x; 1.2109x over previous
#include <cuda_runtime.h>
#include <math.h>

// Problem constants
#define NB       128
#define TLEN     160000
#define NFFT     400
#define HOP      160
#define NFRAMES  1001          // 1 + TLEN/HOP
#define NFREQ    201           // NFFT/2 + 1
#define NMELS    80
#define FPB      32            // frames per block
#define NTILES   ((NFRAMES + FPB - 1) / FPB)   // 32
#define NH       199           // symmetric half: n = 1..199
#define NTHREADS 224
#define SPAN     (HOP * (FPB - 1) + NFFT)      // 5360 samples per block

// Swizzled raw-sample layout: +1 float per 32 so stride-160 (=5*32) accesses
// land on distinct banks (effective stride 165).
#define SWZ(i)   ((i) + ((i) >> 5))
#define SU_SIZE  (FPB * NFREQ)                 // 6432 >= SWZ(SPAN-1)+1 = 5527

// (cos, sin) twiddles. One extra zero row so the prefetch can read row NH.
__device__ float2 g_cs[(NH + 1) * NFREQ];
__device__ int2 g_mrange[NMELS];

__global__ void setup_cs_kernel() {
    int idx = blockIdx.x * blockDim.x + threadIdx.x;
    if (idx >= NH * NFREQ) return;
    int n = idx / NFREQ + 1;            // 1..199
    int k = idx - (n - 1) * NFREQ;      // 0..200
    int r = (n * k) % NFFT;             // exact integer phase reduction
    double a = (double)r * (6.283185307179586476925286766559 / (double)NFFT);
    g_cs[idx] = make_float2((float)cos(a), (float)sin(a));
}

__global__ void setup_mrange_kernel(const float* __restrict__ fb) {
    int m = threadIdx.x;
    if (m >= NMELS) return;
    int ks = NFREQ, ke = 0;
    for (int k = 0; k < NFREQ; k++) {
        if (fb[m * NFREQ + k] != 0.0f) { if (k < ks) ks = k; ke = k + 1; }
    }
    if (ke < ks) { ks = 0; ke = 0; }
    g_mrange[m] = make_int2(ks, ke);
}

// ---- packed fp32x2 helpers (sm_100a) ----
__device__ __forceinline__ unsigned long long pack2(float lo, float hi) {
    unsigned long long r;
    asm("mov.b64 %0, {%1, %2};" : "=l"(r) : "f"(lo), "f"(hi));
    return r;
}
__device__ __forceinline__ void ffma2(unsigned long long& acc,
                                      unsigned long long a,
                                      unsigned long long b) {
    asm("fma.rn.f32x2 %0, %1, %2, %0;" : "+l"(acc) : "l"(a), "l"(b));
}
__device__ __forceinline__ unsigned long long fmul2(unsigned long long a,
                                                    unsigned long long b) {
    unsigned long long r;
    asm("mul.rn.f32x2 %0, %1, %2;" : "=l"(r) : "l"(a), "l"(b));
    return r;
}

__global__ __launch_bounds__(NTHREADS, 2)
void melspec_kernel(const float* __restrict__ audio,
                    const float* __restrict__ window,
                    const float* __restrict__ fb,
                    float* __restrict__ out) {
    // dynamic smem: [0, SU_SIZE)            raw samples (swizzled) / power spectrum
    //               [SU_SIZE, +NH*FPB)      e (even windowed combos), row n = 32 floats
    //               [.., +NH*FPB)           o (odd combos)
    //               [.., +FPB] x0w, [.., +FPB] x200w
    extern __shared__ float smem[];
    float* s_u    = smem;
    float* s_e    = smem + SU_SIZE;
    float* s_o    = s_e + NH * FPB;
    float* s_x0   = s_o + NH * FPB;
    float* s_x200 = s_x0 + FPB;

    const int tid    = threadIdx.x;
    const int b      = blockIdx.y;
    const int tile   = blockIdx.x;
    const int frame0 = tile * FPB;
    const float* x   = audio + (size_t)b * TLEN;
    const int base   = frame0 * HOP - (NFFT / 2);

    // ---- Phase 1: load raw samples with reflect padding (swizzled store) ----
    for (int i = tid; i < SPAN; i += NTHREADS) {
        int j = base + i;
        if (j < 0) j = -j;
        else if (j >= TLEN) j = 2 * TLEN - 2 - j;
        s_u[SWZ(i)] = x[j];
    }
    __syncthreads();

    // ---- Phase 2: even/odd windowed combinations (SoA, conflict-free) ----
    if (tid < FPB) {
        s_x0[tid]   = window[0]        * s_u[SWZ(tid * HOP)];
        s_x200[tid] = window[NFFT / 2] * s_u[SWZ(tid * HOP + NFFT / 2)];
    }
    for (int idx = tid; idx < NH * FPB; idx += NTHREADS) {
        int n = (idx >> 5) + 1;          // FPB == 32
        int f = idx & (FPB - 1);
        float w = window[n];
        float a = s_u[SWZ(f * HOP + n)];
        float c = s_u[SWZ(f * HOP + NFFT - n)];
        s_e[idx] = w * (a + c);
        s_o[idx] = w * (a - c);
    }
    __syncthreads();

    // ---- Phase 3: half-length real DFT via packed f32x2 FMA ----
    unsigned long long ar[FPB / 2], ai[FPB / 2];
    const int k = tid;
    if (k < NFREQ) {
        float sgn = (k & 1) ? -1.0f : 1.0f;
        #pragma unroll
        for (int j = 0; j < FPB / 2; j++) {
            float r0 = s_x0[2 * j]     + sgn * s_x200[2 * j];
            float r1 = s_x0[2 * j + 1] + sgn * s_x200[2 * j + 1];
            ar[j] = pack2(r0, r1);
            ai[j] = 0ULL;
        }
        const float2* csp = g_cs + k;
        float2 cs = csp[0];
        for (int n = 0; n < NH; n++) {
            float2 csn = csp[(n + 1) * NFREQ];   // prefetch (row NH is zeros)
            unsigned long long cc = pack2(cs.x, cs.x);
            unsigned long long ss = pack2(cs.y, cs.y);
            const ulonglong2* e2 = (const ulonglong2*)(s_e + n * FPB);
            const ulonglong2* o2 = (const ulonglong2*)(s_o + n * FPB);
            #pragma unroll
            for (int h = 0; h < FPB / 4; h++) {
                ulonglong2 ev = e2[h];           // smem broadcast, LDS.128
                ulonglong2 ov = o2[h];
                ffma2(ar[2*h],   cc, ev.x);
                ffma2(ar[2*h+1], cc, ev.y);
                ffma2(ai[2*h],   ss, ov.x);
                ffma2(ai[2*h+1], ss, ov.y);
            }
            cs = csn;
        }
    }
    __syncthreads();      // raw samples dead; reuse s_u as power spectrum [k][f]
    if (k < NFREQ) {
        unsigned long long* prow = (unsigned long long*)(s_u + k * FPB);
        #pragma unroll
        for (int j = 0; j < FPB / 2; j++) {
            unsigned long long p = fmul2(ar[j], ar[j]);
            ffma2(p, ai[j], ai[j]);              // p = re^2 + im^2 (packed pair)
            prow[j] = p;
        }
    }
    __syncthreads();

    // ---- Phase 4: sparse mel projection + log ----
    const int f  = tid & (FPB - 1);
    const int mb = tid >> 5;                     // 0..6
    int nvalid = NFRAMES - frame0;
    if (nvalid > FPB) nvalid = FPB;
    for (int m = mb; m < NMELS; m += NTHREADS / FPB) {
        int2 r = g_mrange[m];
        float acc = 0.0f;
        const float* fbr = fb + m * NFREQ;
        for (int kk = r.x; kk < r.y; kk++)
            acc = fmaf(fbr[kk], s_u[kk * FPB + f], acc);
        if (f < nvalid)
            out[((size_t)b * NMELS + m) * NFRAMES + frame0 + f] =
                logf(acc + 1.1920929e-07f);
    }
}

extern "C" void kernel_launch(void* const* d_in, const int* in_sizes, int n_in,
                              void* d_out, int out_size) {
    const float* audio  = (const float*)d_in[0];
    const float* window = (const float*)d_in[1];
    const float* fb     = (const float*)d_in[2];
    float* out          = (float*)d_out;

    const int smem_bytes = (SU_SIZE + 2 * NH * FPB + 2 * FPB) * sizeof(float);
    static int configured = 0;
    if (!configured) {
        cudaFuncSetAttribute(melspec_kernel,
                             cudaFuncAttributeMaxDynamicSharedMemorySize,
                             smem_bytes);
        configured = 1;
    }

    setup_cs_kernel<<<(NH * NFREQ + 255) / 256, 256>>>();
    setup_mrange_kernel<<<1, NMELS>>>(fb);

    dim3 grid(NTILES, NB);
    melspec_kernel<<<grid, NTHREADS, smem_bytes>>>(audio, window, fb, out);
}

// round 4
// speedup vs baseline: 1.5919x; 1.3146x over previous
#include <cuda_runtime.h>
#include <math.h>

// Problem constants
#define NB       128
#define TLEN     160000
#define NFFT     400
#define HOP      160
#define NFRAMES  1001          // 1 + TLEN/HOP
#define NFREQ    201           // NFFT/2 + 1
#define NMELS    80
#define FPB      32            // frames per block
#define NTILES   ((NFRAMES + FPB - 1) / FPB)   // 32
#define NH       199           // symmetric half: n = 1..199
#define NTHREADS 256
#define SPAN     (HOP * (FPB - 1) + NFFT)      // 5360 samples per block

// Swizzled raw-sample layout: +1 float per 32 so stride-160 accesses spread banks.
#define SWZ(i)   ((i) + ((i) >> 5))
#define SU_SIZE  (FPB * NFREQ)                 // 6432 >= SWZ(SPAN-1)+1 = 5527

// Twiddle table, padded: KPAD columns (k), ROWS_PAD rows (r = n-1), rows >= NH zero
#define KPAD     256
#define ROWS_PAD (NH + 2)                      // prefetch distance 2
__device__ float2 g_cs[ROWS_PAD * KPAD];
__device__ int2   g_mrange[NMELS];

// One combined setup kernel (twiddles + mel ranges)
__global__ void setup_kernel(const float* __restrict__ fb) {
    if (blockIdx.x == gridDim.x - 1) {
        int m = threadIdx.x;
        if (m < NMELS) {
            int ks = NFREQ, ke = 0;
            for (int k = 0; k < NFREQ; k++) {
                if (fb[m * NFREQ + k] != 0.0f) { if (k < ks) ks = k; ke = k + 1; }
            }
            if (ke < ks) { ks = 0; ke = 0; }
            g_mrange[m] = make_int2(ks, ke);
        }
        return;
    }
    int idx = blockIdx.x * blockDim.x + threadIdx.x;
    if (idx >= ROWS_PAD * KPAD) return;
    int r = idx / KPAD;                 // r = n-1, n = 1..199 real rows
    int k = idx - r * KPAD;
    float2 v = make_float2(0.0f, 0.0f);
    if (r < NH) {
        long long p = ((long long)(r + 1) * (long long)k) % NFFT;
        double a = (double)p * (6.283185307179586476925286766559 / (double)NFFT);
        v = make_float2((float)cos(a), (float)sin(a));
    }
    g_cs[idx] = v;
}

// ---- packed fp32x2 helpers (sm_100a) ----
__device__ __forceinline__ unsigned long long pack2(float lo, float hi) {
    unsigned long long r;
    asm("mov.b64 %0, {%1, %2};" : "=l"(r) : "f"(lo), "f"(hi));
    return r;
}
__device__ __forceinline__ void unpack2(unsigned long long v, float& lo, float& hi) {
    asm("mov.b64 {%0, %1}, %2;" : "=f"(lo), "=f"(hi) : "l"(v));
}
__device__ __forceinline__ void ffma2(unsigned long long& acc,
                                      unsigned long long a,
                                      unsigned long long b) {
    asm("fma.rn.f32x2 %0, %1, %2, %0;" : "+l"(acc) : "l"(a), "l"(b));
}

__global__ __launch_bounds__(NTHREADS, 2)
void melspec_kernel(const float* __restrict__ audio,
                    const float* __restrict__ window,
                    const float* __restrict__ fb,
                    float* __restrict__ out) {
    // dynamic smem:
    //  [0, SU_SIZE)        raw samples (swizzled) -> later power spectrum [f][k], stride NFREQ
    //  [SU_SIZE, +NH*FPB)  e combos, row n = 32 floats
    //  [.., +NH*FPB)       o combos
    //  [.., +FPB]          x0w   [.., +FPB] x200w
    extern __shared__ float smem[];
    float* s_u    = smem;
    float* s_e    = smem + SU_SIZE;
    float* s_o    = s_e + NH * FPB;
    float* s_x0   = s_o + NH * FPB;
    float* s_x200 = s_x0 + FPB;

    const int tid    = threadIdx.x;
    const int b      = blockIdx.y;
    const int tile   = blockIdx.x;
    const int frame0 = tile * FPB;
    const float* x   = audio + (size_t)b * TLEN;
    const int base   = frame0 * HOP - (NFFT / 2);

    // ---- Phase 1: load raw samples with reflect padding (swizzled store) ----
    for (int i = tid; i < SPAN; i += NTHREADS) {
        int j = base + i;
        if (j < 0) j = -j;
        else if (j >= TLEN) j = 2 * TLEN - 2 - j;
        s_u[SWZ(i)] = x[j];
    }
    __syncthreads();

    // ---- Phase 2: even/odd windowed combinations (SoA, conflict-free) ----
    if (tid < FPB) {
        s_x0[tid]   = window[0]        * s_u[SWZ(tid * HOP)];
        s_x200[tid] = window[NFFT / 2] * s_u[SWZ(tid * HOP + NFFT / 2)];
    }
    for (int idx = tid; idx < NH * FPB; idx += NTHREADS) {
        int n = (idx >> 5) + 1;          // FPB == 32
        int f = idx & (FPB - 1);
        float w = window[n];
        float a = s_u[SWZ(f * HOP + n)];
        float c = s_u[SWZ(f * HOP + NFFT - n)];
        s_e[idx] = w * (a + c);
        s_o[idx] = w * (a - c);
    }
    __syncthreads();

    // ---- Phase 3: half-length real DFT, Kt=4 bins x Ft=8 frames per thread ----
    // thread -> (kt = tid&63 handles k in {kt, kt+64, kt+128, kt+192},
    //            group g = tid>>6 handles frames [8g, 8g+8))
    const int kt  = tid & 63;
    const int g   = tid >> 6;
    const int fb0 = g * 8;

    unsigned long long ar[4][4], ai[4][4];
    {
        float sgn = (kt & 1) ? -1.0f : 1.0f;   // parity of k = parity of kt
        unsigned long long init[4];
        #pragma unroll
        for (int h = 0; h < 4; h++) {
            float r0 = s_x0[fb0 + 2*h]     + sgn * s_x200[fb0 + 2*h];
            float r1 = s_x0[fb0 + 2*h + 1] + sgn * s_x200[fb0 + 2*h + 1];
            init[h] = pack2(r0, r1);
        }
        #pragma unroll
        for (int j = 0; j < 4; j++)
            #pragma unroll
            for (int h = 0; h < 4; h++) { ar[j][h] = init[h]; ai[j][h] = 0ULL; }
    }

    // twiddle software pipeline, prefetch distance 2
    float2 csA[4], csB[4];
    #pragma unroll
    for (int j = 0; j < 4; j++) csA[j] = g_cs[0 * KPAD + kt + 64 * j];
    #pragma unroll
    for (int j = 0; j < 4; j++) csB[j] = g_cs[1 * KPAD + kt + 64 * j];

    for (int n = 0; n < NH; n++) {
        float2 csN[4];
        #pragma unroll
        for (int j = 0; j < 4; j++)
            csN[j] = g_cs[(n + 2) * KPAD + kt + 64 * j];   // rows >= NH are zeros

        const ulonglong2* e2 = (const ulonglong2*)(s_e + n * FPB + fb0);
        const ulonglong2* o2 = (const ulonglong2*)(s_o + n * FPB + fb0);
        ulonglong2 eva = e2[0], evb = e2[1];
        ulonglong2 ova = o2[0], ovb = o2[1];

        #pragma unroll
        for (int j = 0; j < 4; j++) {
            unsigned long long cc = pack2(csA[j].x, csA[j].x);
            unsigned long long ss = pack2(csA[j].y, csA[j].y);
            ffma2(ar[j][0], cc, eva.x);
            ffma2(ar[j][1], cc, eva.y);
            ffma2(ar[j][2], cc, evb.x);
            ffma2(ar[j][3], cc, evb.y);
            ffma2(ai[j][0], ss, ova.x);
            ffma2(ai[j][1], ss, ova.y);
            ffma2(ai[j][2], ss, ovb.x);
            ffma2(ai[j][3], ss, ovb.y);
        }
        #pragma unroll
        for (int j = 0; j < 4; j++) { csA[j] = csB[j]; csB[j] = csN[j]; }
    }
    __syncthreads();     // raw samples dead; reuse s_u as power spectrum [f][k]

    #pragma unroll
    for (int j = 0; j < 4; j++) {
        int k = kt + 64 * j;
        if (k < NFREQ) {
            #pragma unroll
            for (int h = 0; h < 4; h++) {
                float r0, r1, i0, i1;
                unpack2(ar[j][h], r0, r1);
                unpack2(ai[j][h], i0, i1);
                s_u[(fb0 + 2*h)     * NFREQ + k] = r0 * r0 + i0 * i0;
                s_u[(fb0 + 2*h + 1) * NFREQ + k] = r1 * r1 + i1 * i1;
            }
        }
    }
    __syncthreads();

    // ---- Phase 4: sparse mel projection + log ----
    const int f  = tid & (FPB - 1);
    const int mb = tid >> 5;                     // 0..7
    int nvalid = NFRAMES - frame0;
    if (nvalid > FPB) nvalid = FPB;
    const float* pr = s_u + f * NFREQ;
    for (int m = mb; m < NMELS; m += NTHREADS / FPB) {
        int2 r = g_mrange[m];
        float acc = 0.0f;
        const float* fbr = fb + m * NFREQ;
        for (int kk = r.x; kk < r.y; kk++)
            acc = fmaf(fbr[kk], pr[kk], acc);
        if (f < nvalid)
            out[((size_t)b * NMELS + m) * NFRAMES + frame0 + f] =
                logf(acc + 1.1920929e-07f);
    }
}

extern "C" void kernel_launch(void* const* d_in, const int* in_sizes, int n_in,
                              void* d_out, int out_size) {
    const float* audio  = (const float*)d_in[0];
    const float* window = (const float*)d_in[1];
    const float* fb     = (const float*)d_in[2];
    float* out          = (float*)d_out;

    const int smem_bytes = (SU_SIZE + 2 * NH * FPB + 2 * FPB) * sizeof(float);
    cudaFuncSetAttribute(melspec_kernel,
                         cudaFuncAttributeMaxDynamicSharedMemorySize,
                         smem_bytes);

    int setup_blocks = (ROWS_PAD * KPAD + 255) / 256 + 1;   // last block: mrange
    setup_kernel<<<setup_blocks, 256>>>(fb);

    dim3 grid(NTILES, NB);
    melspec_kernel<<<grid, NTHREADS, smem_bytes>>>(audio, window, fb, out);
}